// round 3
// baseline (speedup 1.0000x reference)
#include <cuda_runtime.h>
#include <math.h>

// CroquetGNN: 2-layer GCN, N<=100000 nodes, E<=3200000 edges, feat 3 -> 16 -> 1
// out = sigmoid( GCNConv2( relu( GCNConv1(x) ) ) )
// Restructured: dinv[d] * segsum_{s->d}( dinv[s]*x[s] ) @ W (+ self loop + b),
// with edges binned by destination so scatter-adds happen in shared memory.

#define MAXN 100000
#define MAXE 3200000
#define TB 256
#define EPT 4            // edges per thread in the binning pass
#define NPB 256          // nodes per destination bin
#define NPB_SHIFT 8
#define BINS ((MAXN + NPB - 1) / NPB)   // 391
#define CAP 16384        // bucket capacity (mean ~8184 for uniform graph)

// ---- scratch (static device globals; no allocation anywhere) ----
__device__ int      g_is64;               // 1 if edge_index is int64
__device__ unsigned g_binned[BINS * CAP]; // packed edges: src | (dloc<<17)
__device__ int      g_bincnt[BINS];
__device__ float    g_dinv[MAXN];         // rsqrt(deg)
__device__ float4   g_xd[MAXN];           // dinv[i] * x[i]
__device__ float    g_gd[MAXN];           // dinv[i] * (relu(conv1) . W2)

// ---- init: zero bin counters + dtype detect ----
__global__ void __launch_bounds__(512) k_init(const int* __restrict__ idx) {
    int t = threadIdx.x;
    if (t < BINS) g_bincnt[t] = 0;
    if (t == 0) {
        // int64 little-endian with values < 2^31 has all-zero hi words
        int is64 = 1;
        for (int j = 0; j < 64; j++) {
            if (idx[2 * j + 1] != 0) { is64 = 0; break; }
        }
        g_is64 = is64;
    }
}

// ---- bin pass: pack (src, dloc) and scatter into destination bins ----
__global__ void __launch_bounds__(TB) k_bin(const int* __restrict__ idx, int E) {
    int tid = blockIdx.x * blockDim.x + threadIdx.x;
    int stride = gridDim.x * blockDim.x;
    int s[EPT], d[EPT];
    if (g_is64) {
        const long long* __restrict__ p = (const long long*)idx;
#pragma unroll
        for (int k = 0; k < EPT; k++) {
            int e = tid + k * stride;
            if (e < E) { s[k] = (int)__ldg(&p[e]); d[k] = (int)__ldg(&p[E + e]); }
        }
    } else {
#pragma unroll
        for (int k = 0; k < EPT; k++) {
            int e = tid + k * stride;
            if (e < E) { s[k] = __ldg(&idx[e]); d[k] = __ldg(&idx[E + e]); }
        }
    }
#pragma unroll
    for (int k = 0; k < EPT; k++) {
        int e = tid + k * stride;
        if (e < E) {
            int b = d[k] >> NPB_SHIFT;
            unsigned packed = (unsigned)s[k] | ((unsigned)(d[k] & (NPB - 1)) << 17);
            int pos = atomicAdd(&g_bincnt[b], 1);
            if (pos < CAP) g_binned[b * CAP + pos] = packed;
        }
    }
}

// ---- per-bin degree histogram (smem) fused with dinv + xd computation ----
__global__ void __launch_bounds__(NPB) k_deg_xd(const float* __restrict__ x, int N) {
    __shared__ int cnt[NPB];
    int t = threadIdx.x, b = blockIdx.x;
    cnt[t] = 0;
    __syncthreads();
    int n = min(g_bincnt[b], CAP);
    const unsigned* __restrict__ ebase = g_binned + (size_t)b * CAP;
    for (int e = t; e < n; e += NPB) {
        atomicAdd(&cnt[ebase[e] >> 17], 1);
    }
    __syncthreads();
    int node = b * NPB + t;
    if (node < N) {
        float di = rsqrtf((float)(cnt[t] + 1));   // +1 self loop
        g_dinv[node] = di;
        g_xd[node] = make_float4(x[3 * node] * di, x[3 * node + 1] * di,
                                 x[3 * node + 2] * di, 0.f);
    }
}

// ---- layer-1 aggregation in smem + fused epilogue (W1, b1, relu, W2, dinv) ----
__global__ void __launch_bounds__(NPB) k_agg1(const float* __restrict__ W1,
                                              const float* __restrict__ b1,
                                              const float* __restrict__ W2, int N) {
    __shared__ float sx[NPB * 3];
    __shared__ float sW1[48], sb1[16], sW2[16];
    int t = threadIdx.x, b = blockIdx.x;
    sx[t] = 0.f; sx[t + NPB] = 0.f; sx[t + 2 * NPB] = 0.f;
    if (t < 48) sW1[t] = W1[t];
    if (t < 16) { sb1[t] = b1[t]; sW2[t] = W2[t]; }
    __syncthreads();
    int n = min(g_bincnt[b], CAP);
    const unsigned* __restrict__ ebase = g_binned + (size_t)b * CAP;

    int e = t;
    // 4-deep batches for gather MLP
    for (; e + 3 * NPB < n; e += 4 * NPB) {
        unsigned p0 = ebase[e], p1 = ebase[e + NPB], p2 = ebase[e + 2 * NPB], p3 = ebase[e + 3 * NPB];
        float4 v0 = g_xd[p0 & 0x1FFFF];
        float4 v1 = g_xd[p1 & 0x1FFFF];
        float4 v2 = g_xd[p2 & 0x1FFFF];
        float4 v3 = g_xd[p3 & 0x1FFFF];
        int d0 = (p0 >> 17) * 3, d1 = (p1 >> 17) * 3, d2 = (p2 >> 17) * 3, d3 = (p3 >> 17) * 3;
        atomicAdd(&sx[d0], v0.x); atomicAdd(&sx[d0 + 1], v0.y); atomicAdd(&sx[d0 + 2], v0.z);
        atomicAdd(&sx[d1], v1.x); atomicAdd(&sx[d1 + 1], v1.y); atomicAdd(&sx[d1 + 2], v1.z);
        atomicAdd(&sx[d2], v2.x); atomicAdd(&sx[d2 + 1], v2.y); atomicAdd(&sx[d2 + 2], v2.z);
        atomicAdd(&sx[d3], v3.x); atomicAdd(&sx[d3 + 1], v3.y); atomicAdd(&sx[d3 + 2], v3.z);
    }
    for (; e < n; e += NPB) {
        unsigned p = ebase[e];
        float4 v = g_xd[p & 0x1FFFF];
        int dd = (p >> 17) * 3;
        atomicAdd(&sx[dd], v.x); atomicAdd(&sx[dd + 1], v.y); atomicAdd(&sx[dd + 2], v.z);
    }
    __syncthreads();

    int node = b * NPB + t;
    if (node < N) {
        float di = g_dinv[node];
        float4 xd = g_xd[node];     // self-loop contribution: di * xd
        float v0 = di * (sx[t * 3] + xd.x);
        float v1 = di * (sx[t * 3 + 1] + xd.y);
        float v2 = di * (sx[t * 3 + 2] + xd.z);
        float g = 0.f;
#pragma unroll
        for (int c = 0; c < 16; c++) {
            float h = fmaf(v0, sW1[c], fmaf(v1, sW1[16 + c], fmaf(v2, sW1[32 + c], sb1[c])));
            h = fmaxf(h, 0.f);
            g = fmaf(h, sW2[c], g);
        }
        g_gd[node] = g * di;
    }
}

// ---- layer-2 aggregation in smem + fused epilogue (dinv, b2, sigmoid) ----
__global__ void __launch_bounds__(NPB) k_agg2(const float* __restrict__ b2,
                                              float* __restrict__ out, int N) {
    __shared__ float sg[NPB];
    int t = threadIdx.x, b = blockIdx.x;
    sg[t] = 0.f;
    __syncthreads();
    int n = min(g_bincnt[b], CAP);
    const unsigned* __restrict__ ebase = g_binned + (size_t)b * CAP;

    int e = t;
    for (; e + 3 * NPB < n; e += 4 * NPB) {
        unsigned p0 = ebase[e], p1 = ebase[e + NPB], p2 = ebase[e + 2 * NPB], p3 = ebase[e + 3 * NPB];
        float v0 = g_gd[p0 & 0x1FFFF];
        float v1 = g_gd[p1 & 0x1FFFF];
        float v2 = g_gd[p2 & 0x1FFFF];
        float v3 = g_gd[p3 & 0x1FFFF];
        atomicAdd(&sg[p0 >> 17], v0);
        atomicAdd(&sg[p1 >> 17], v1);
        atomicAdd(&sg[p2 >> 17], v2);
        atomicAdd(&sg[p3 >> 17], v3);
    }
    for (; e < n; e += NPB) {
        unsigned p = ebase[e];
        atomicAdd(&sg[p >> 17], g_gd[p & 0x1FFFF]);
    }
    __syncthreads();

    int node = b * NPB + t;
    if (node < N) {
        float di = g_dinv[node];
        float s = di * (sg[t] + g_gd[node]) + b2[0];
        out[node] = 1.0f / (1.0f + expf(-s));
    }
}

extern "C" void kernel_launch(void* const* d_in, const int* in_sizes, int n_in,
                              void* d_out, int out_size) {
    const float* x   = (const float*)d_in[0];
    const int*   idx = (const int*)d_in[1];   // int32 or int64 (detected on device)
    const float* W1  = (const float*)d_in[2];
    const float* b1  = (const float*)d_in[3];
    const float* W2  = (const float*)d_in[4];
    const float* b2  = (const float*)d_in[5];
    float* out = (float*)d_out;

    int N_ = in_sizes[0] / 3;   // 100000
    int E_ = in_sizes[1] / 2;   // 3200000

    int nbins = (N_ + NPB - 1) / NPB;
    int threads_e = (E_ + EPT - 1) / EPT;
    int nb_e = (threads_e + TB - 1) / TB;

    k_init<<<1, 512>>>(idx);
    k_bin<<<nb_e, TB>>>(idx, E_);
    k_deg_xd<<<nbins, NPB>>>(x, N_);
    k_agg1<<<nbins, NPB>>>(W1, b1, W2, N_);
    k_agg2<<<nbins, NPB>>>(b2, out, N_);
}

// round 4
// speedup vs baseline: 5.0241x; 5.0241x over previous
#include <cuda_runtime.h>
#include <math.h>

// CroquetGNN: 2-layer GCN, N=100000, E=3200000, feat 3 -> 16 -> 1
// out = sigmoid( GCNConv2( relu( GCNConv1(x) ) ) )
// GCNConv(x) = dinv[d] * segsum_{s->d}( dinv[s]*x[s] ) @ W (+ self loop + b)
//
// Single persistent kernel; phases separated by software grid barriers.
// Scratch is self-restoring (consumer resets to zero) so graph replays are valid.

#define MAXN 100000
#define MAXE 3200000
#define TB 256
#define BPSM 4   // resident blocks per SM (guaranteed by launch_bounds)

// ---- scratch (static device globals, BSS-zeroed at load; no allocation) ----
__device__ int2   g_edge[MAXE];    // converted (src,dst) int32 pairs
__device__ int    g_deg[MAXN];     // in-degree count   (reset to 0 in phase B)
__device__ float  g_dinv[MAXN];    // rsqrt(deg+1)
__device__ float4 g_xd[MAXN];      // dinv[i] * x[i] (padded)
__device__ float4 g_xagg[MAXN];    // layer-1 agg       (reset to 0 in phase D)
__device__ float  g_gd[MAXN];      // dinv[i]*(relu(conv1).W2)
__device__ float  g_gagg[MAXN];    // layer-2 agg       (reset to 0 in phase F)
__device__ int    g_count;         // barrier arrivals (self-resetting)
__device__ volatile int g_sense;   // barrier sense (read relatively -> replay-safe)

struct Smem {
    int sense;
    int is64;
    float W1[48], b1[16], W2[16];
};

__device__ __forceinline__ void gridbar(Smem* sm, int nblocks) {
    __syncthreads();
    if (threadIdx.x == 0) {
        int s = sm->sense ^ 1;
        sm->sense = s;
        __threadfence();                       // publish this block's writes
        if (atomicAdd(&g_count, 1) == nblocks - 1) {
            g_count = 0;
            __threadfence();                   // order count reset before release
            g_sense = s;
        } else {
            while (g_sense != s) { }
            __threadfence();                   // acquire
        }
    }
    __syncthreads();
}

__global__ void __launch_bounds__(TB, BPSM)
k_gcn(const float* __restrict__ x, const int* __restrict__ idx,
      const float* __restrict__ W1, const float* __restrict__ b1,
      const float* __restrict__ W2, const float* __restrict__ b2,
      float* __restrict__ out, int N, int E) {
    __shared__ Smem sm;
    int t = threadIdx.x;
    int tid = blockIdx.x * TB + t;
    int nthreads = gridDim.x * TB;
    int nblocks = gridDim.x;

    if (t == 0) {
        sm.sense = g_sense;   // relative sense: works whatever parity a replay starts at
        // dtype detect: int64 little-endian with values < 2^31 has all-zero hi words
        int is64 = 1;
        for (int j = 0; j < 64; j++)
            if (idx[2 * j + 1] != 0) { is64 = 0; break; }
        sm.is64 = is64;
    }
    __syncthreads();
    int is64 = sm.is64;

    // ---- phase A: convert edges to int2 + degree count (RED to L2) ----
    if (is64) {
        const long long* __restrict__ p = (const long long*)idx;
#pragma unroll 4
        for (int e = tid; e < E; e += nthreads) {
            int s = (int)__ldg(&p[e]);
            int d = (int)__ldg(&p[E + e]);
            g_edge[e] = make_int2(s, d);
            atomicAdd(&g_deg[d], 1);
        }
    } else {
#pragma unroll 4
        for (int e = tid; e < E; e += nthreads) {
            int s = __ldg(&idx[e]);
            int d = __ldg(&idx[E + e]);
            g_edge[e] = make_int2(s, d);
            atomicAdd(&g_deg[d], 1);
        }
    }
    gridbar(&sm, nblocks);

    // ---- phase B: dinv = rsqrt(deg+1); xd = dinv*x; reset deg ----
    for (int i = tid; i < N; i += nthreads) {
        int dg = g_deg[i];
        g_deg[i] = 0;                          // restore for next replay
        float di = rsqrtf((float)(dg + 1));    // +1 self loop
        g_dinv[i] = di;
        g_xd[i] = make_float4(x[3 * i] * di, x[3 * i + 1] * di,
                              x[3 * i + 2] * di, 0.f);
    }
    gridbar(&sm, nblocks);

    // ---- phase C: layer-1 edge aggregation: xagg[d] += xd[s] (one v4 RED/edge) ----
#pragma unroll 4
    for (int e = tid; e < E; e += nthreads) {
        int2 ed = g_edge[e];
        float4 v = g_xd[ed.x];
        float* dst = (float*)&g_xagg[ed.y];
        asm volatile("red.global.add.v4.f32 [%0], {%1, %2, %3, %4};"
                     :: "l"(dst), "f"(v.x), "f"(v.y), "f"(v.z), "f"(v.w)
                     : "memory");
    }
    gridbar(&sm, nblocks);

    // ---- phase D: node epilogue 1 (self loop, dinv, W1, b1, relu, .W2, dinv); reset xagg ----
    if (t < 48) sm.W1[t] = W1[t];
    if (t < 16) { sm.b1[t] = b1[t]; sm.W2[t] = W2[t]; }
    __syncthreads();
    for (int i = tid; i < N; i += nthreads) {
        float di = g_dinv[i];
        float4 a = g_xagg[i];
        g_xagg[i] = make_float4(0.f, 0.f, 0.f, 0.f);   // restore for next replay
        float4 xd = g_xd[i];
        // self-loop contributes dinv[i]^2 * x[i] = dinv[i] * xd[i]
        float v0 = di * (a.x + xd.x);
        float v1 = di * (a.y + xd.y);
        float v2 = di * (a.z + xd.z);
        float g = 0.f;
#pragma unroll
        for (int c = 0; c < 16; c++) {
            float h = fmaf(v0, sm.W1[c], fmaf(v1, sm.W1[16 + c],
                      fmaf(v2, sm.W1[32 + c], sm.b1[c])));
            h = fmaxf(h, 0.f);
            g = fmaf(h, sm.W2[c], g);
        }
        g_gd[i] = g * di;
    }
    gridbar(&sm, nblocks);

    // ---- phase E: layer-2 edge aggregation: gagg[d] += gd[s] ----
#pragma unroll 4
    for (int e = tid; e < E; e += nthreads) {
        int2 ed = g_edge[e];
        atomicAdd(&g_gagg[ed.y], g_gd[ed.x]);
    }
    gridbar(&sm, nblocks);

    // ---- phase F: node epilogue 2 (self loop, dinv, b2, sigmoid); reset gagg ----
    float bias2 = __ldg(&b2[0]);
    for (int i = tid; i < N; i += nthreads) {
        float di = g_dinv[i];
        float ga = g_gagg[i];
        g_gagg[i] = 0.f;                       // restore for next replay
        float s = di * (ga + g_gd[i]) + bias2;
        out[i] = 1.0f / (1.0f + expf(-s));
    }
}

extern "C" void kernel_launch(void* const* d_in, const int* in_sizes, int n_in,
                              void* d_out, int out_size) {
    const float* x   = (const float*)d_in[0];
    const int*   idx = (const int*)d_in[1];   // int32 or int64 (detected on device)
    const float* W1  = (const float*)d_in[2];
    const float* b1  = (const float*)d_in[3];
    const float* W2  = (const float*)d_in[4];
    const float* b2  = (const float*)d_in[5];
    float* out = (float*)d_out;

    int N_ = in_sizes[0] / 3;   // 100000
    int E_ = in_sizes[1] / 2;   // 3200000

    int dev = 0, sms = 148;
    cudaGetDevice(&dev);
    cudaDeviceGetAttribute(&sms, cudaDevAttrMultiProcessorCount, dev);
    int grid = sms * BPSM;      // all blocks resident (launch_bounds guarantees)

    k_gcn<<<grid, TB>>>(x, idx, W1, b1, W2, b2, out, N_, E_);
}

// round 5
// speedup vs baseline: 6.7732x; 1.3481x over previous
#include <cuda_runtime.h>
#include <math.h>

// CroquetGNN: 2-layer GCN, N=100000, E=3200000, feat 3 -> 16 -> 1
// out = sigmoid( GCNConv2( relu( GCNConv1(x) ) ) )
// GCNConv(x) = dinv[d] * segsum_{s->d}( dinv[s]*x[s] ) @ W (+ self loop + b)
//
// Multi-kernel, consumer-reset scratch (no init kernel), int32 fast path
// (no edge conversion write; edge kernels read the raw index rows).

#define MAXN 100000
#define MAXE 3200000
#define TB 256

// ---- scratch (static device globals, BSS-zeroed at load; no allocation) ----
__device__ int    g_is64;          // published by k_count block 0
__device__ int2   g_edge[MAXE];    // converted pairs (int64 input path only)
__device__ int    g_deg[MAXN];     // in-degree   (reset to 0 in k_xd)
__device__ float  g_dinv[MAXN];    // rsqrt(deg+1)
__device__ float4 g_xd[MAXN];      // dinv[i] * x[i] (padded)
__device__ float4 g_xagg[MAXN];    // layer-1 agg (reset in k_node1)
__device__ float  g_gd[MAXN];      // dinv[i]*(relu(conv1).W2)
__device__ float  g_gagg[MAXN];    // layer-2 agg (reset in k_node2)

// per-block dtype detect: int64 LE with values < 2^31 has all-zero hi words
__device__ __forceinline__ int detect64_block(const int* __restrict__ idx) {
    __shared__ int s64;
    if (threadIdx.x < 32) {
        int hi = __ldg(&idx[2 * threadIdx.x + 1]);
        unsigned m = __ballot_sync(0xFFFFFFFFu, hi == 0);
        if (threadIdx.x == 0) s64 = (m == 0xFFFFFFFFu);
    }
    __syncthreads();
    return s64;
}

// ---- k_count: degree count (+ conversion only on the int64 path) ----
__global__ void __launch_bounds__(TB) k_count(const int* __restrict__ idx, int E) {
    int is64 = detect64_block(idx);
    int e = blockIdx.x * TB + threadIdx.x;
    if (e == 0) g_is64 = is64;               // publish for later kernels
    if (e >= E) return;
    if (is64) {
        const long long* __restrict__ p = (const long long*)idx;
        int s = (int)__ldg(&p[e]);
        int d = (int)__ldg(&p[E + e]);
        g_edge[e] = make_int2(s, d);
        atomicAdd(&g_deg[d], 1);
    } else {
        int d = __ldg(&idx[E + e]);          // dst row only
        atomicAdd(&g_deg[d], 1);
    }
}

// ---- k_xd: dinv = rsqrt(deg+1); xd = dinv*x; reset deg ----
__global__ void __launch_bounds__(TB) k_xd(const float* __restrict__ x, int N) {
    int i = blockIdx.x * TB + threadIdx.x;
    if (i >= N) return;
    int dg = g_deg[i];
    g_deg[i] = 0;                            // consumer reset (replay-safe)
    float di = rsqrtf((float)(dg + 1));      // +1 self loop
    g_dinv[i] = di;
    g_xd[i] = make_float4(x[3 * i] * di, x[3 * i + 1] * di,
                          x[3 * i + 2] * di, 0.f);
}

// ---- k_edge1: xagg[d] += xd[s]  (one v4 RED per edge) ----
__global__ void __launch_bounds__(TB) k_edge1(const int* __restrict__ idx, int E) {
    int e = blockIdx.x * TB + threadIdx.x;
    if (e >= E) return;
    int s, d;
    if (g_is64) { int2 ed = g_edge[e]; s = ed.x; d = ed.y; }
    else        { s = __ldg(&idx[e]);  d = __ldg(&idx[E + e]); }
    float4 v = g_xd[s];
    float* dst = (float*)&g_xagg[d];
    asm volatile("red.global.add.v4.f32 [%0], {%1, %2, %3, %4};"
                 :: "l"(dst), "f"(v.x), "f"(v.y), "f"(v.z), "f"(v.w)
                 : "memory");
}

// ---- k_node1: finish conv1 (+self loop, dinv, b1), relu, .W2, scale dinv; reset xagg ----
__global__ void __launch_bounds__(TB) k_node1(const float* __restrict__ W1,
                                              const float* __restrict__ b1,
                                              const float* __restrict__ W2, int N) {
    __shared__ float sW1[48], sb1[16], sW2[16];
    int t = threadIdx.x;
    if (t < 48) sW1[t] = W1[t];
    if (t < 16) { sb1[t] = b1[t]; sW2[t] = W2[t]; }
    __syncthreads();
    int i = blockIdx.x * TB + t;
    if (i >= N) return;
    float di = g_dinv[i];
    float4 a = g_xagg[i];
    g_xagg[i] = make_float4(0.f, 0.f, 0.f, 0.f);   // consumer reset
    float4 xd = g_xd[i];
    // self-loop contributes dinv[i]^2 * x[i] = dinv[i] * xd[i]
    float v0 = di * (a.x + xd.x);
    float v1 = di * (a.y + xd.y);
    float v2 = di * (a.z + xd.z);
    float g = 0.f;
#pragma unroll
    for (int c = 0; c < 16; c++) {
        float h = fmaf(v0, sW1[c], fmaf(v1, sW1[16 + c], fmaf(v2, sW1[32 + c], sb1[c])));
        h = fmaxf(h, 0.f);
        g = fmaf(h, sW2[c], g);
    }
    g_gd[i] = g * di;
}

// ---- k_edge2: gagg[d] += gd[s] ----
__global__ void __launch_bounds__(TB) k_edge2(const int* __restrict__ idx, int E) {
    int e = blockIdx.x * TB + threadIdx.x;
    if (e >= E) return;
    int s, d;
    if (g_is64) { int2 ed = g_edge[e]; s = ed.x; d = ed.y; }
    else        { s = __ldg(&idx[e]);  d = __ldg(&idx[E + e]); }
    float v = g_gd[s];
    asm volatile("red.global.add.f32 [%0], %1;"
                 :: "l"(&g_gagg[d]), "f"(v) : "memory");
}

// ---- k_node2: finish conv2 (+self loop, dinv, b2), sigmoid; reset gagg ----
__global__ void __launch_bounds__(TB) k_node2(const float* __restrict__ b2,
                                              float* __restrict__ out, int N) {
    int i = blockIdx.x * TB + threadIdx.x;
    if (i >= N) return;
    float di = g_dinv[i];
    float ga = g_gagg[i];
    g_gagg[i] = 0.f;                         // consumer reset
    float s = di * (ga + g_gd[i]) + __ldg(&b2[0]);
    out[i] = 1.0f / (1.0f + expf(-s));
}

extern "C" void kernel_launch(void* const* d_in, const int* in_sizes, int n_in,
                              void* d_out, int out_size) {
    const float* x   = (const float*)d_in[0];
    const int*   idx = (const int*)d_in[1];   // int32 or int64 (device-detected)
    const float* W1  = (const float*)d_in[2];
    const float* b1  = (const float*)d_in[3];
    const float* W2  = (const float*)d_in[4];
    const float* b2  = (const float*)d_in[5];
    float* out = (float*)d_out;

    int N_ = in_sizes[0] / 3;   // 100000
    int E_ = in_sizes[1] / 2;   // 3200000

    int nb_n = (N_ + TB - 1) / TB;
    int nb_e = (E_ + TB - 1) / TB;

    k_count<<<nb_e, TB>>>(idx, E_);
    k_xd   <<<nb_n, TB>>>(x, N_);
    k_edge1<<<nb_e, TB>>>(idx, E_);
    k_node1<<<nb_n, TB>>>(W1, b1, W2, N_);
    k_edge2<<<nb_e, TB>>>(idx, E_);
    k_node2<<<nb_n, TB>>>(b2, out, N_);
}